// round 3
// baseline (speedup 1.0000x reference)
#include <cuda_runtime.h>
#include <math.h>

// Closed-form reduction of the 4-qubit circuit:
//   z = cosB * cos(t1)cos(t2)cos(t3) - sinB*cos(phi0)*cos(phi1) * sin(t0)sin(t1)
//   t_i = tanh(W1[i]*x + b1[i]) + qw[0,i],  |t_i| < ~1.5
// sin/cos via Taylor polynomials (|t|<1.5: err < 2e-5), tanh via ex2+rcp.
// 4 samples per thread, lane-transposed for coalescing.

__device__ __forceinline__ float tanh_from_scaled(float q) {
    // tanh(p) where q = 2*log2(e)*p pre-scaled: tanh = 1 - 2/(exp2(q)+1)
    float e;
    asm("ex2.approx.f32 %0, %1;" : "=f"(e) : "f"(q));
    float d = e + 1.0f;
    float r;
    asm("rcp.approx.f32 %0, %1;" : "=f"(r) : "f"(d));
    return fmaf(-2.0f, r, 1.0f);
}

// sin(x), |x| <= ~1.6 : deg-9 Taylor, abs err < 2e-6 at 1.5
__device__ __forceinline__ float sin_poly(float x, float y /* = x*x */) {
    float p = fmaf(y, 2.7557319e-6f, -1.9841270e-4f);
    p = fmaf(y, p, 8.3333333e-3f);
    p = fmaf(y, p, -1.6666667e-1f);
    p = fmaf(y, p, 1.0f);
    return x * p;
}

// cos(x), |x| <= ~1.6 : deg-8 Taylor, abs err < 2e-5 at 1.5
__device__ __forceinline__ float cos_poly(float y /* = x*x */) {
    float p = fmaf(y, 2.4801587e-5f, -1.3888889e-3f);
    p = fmaf(y, p, 4.1666667e-2f);
    p = fmaf(y, p, -5.0e-1f);
    p = fmaf(y, p, 1.0f);
    return p;
}

__device__ __forceinline__ float2 sample_eval(const float* __restrict__ sp, float4 xv) {
    float q0 = fmaf(sp[0],  xv.x, fmaf(sp[1],  xv.y, fmaf(sp[2],  xv.z, fmaf(sp[3],  xv.w, sp[16]))));
    float q1 = fmaf(sp[4],  xv.x, fmaf(sp[5],  xv.y, fmaf(sp[6],  xv.z, fmaf(sp[7],  xv.w, sp[17]))));
    float q2 = fmaf(sp[8],  xv.x, fmaf(sp[9],  xv.y, fmaf(sp[10], xv.z, fmaf(sp[11], xv.w, sp[18]))));
    float q3 = fmaf(sp[12], xv.x, fmaf(sp[13], xv.y, fmaf(sp[14], xv.z, fmaf(sp[15], xv.w, sp[19]))));

    float t0 = tanh_from_scaled(q0) + sp[20];
    float t1 = tanh_from_scaled(q1) + sp[21];
    float t2 = tanh_from_scaled(q2) + sp[22];
    float t3 = tanh_from_scaled(q3) + sp[23];

    float y0 = t0 * t0, y1 = t1 * t1, y2 = t2 * t2, y3 = t3 * t3;

    float st0 = sin_poly(t0, y0);
    float st1 = sin_poly(t1, y1);
    float ct1 = cos_poly(y1);
    float ct2 = cos_poly(y2);
    float ct3 = cos_poly(y3);

    float z = sp[24] * (ct1 * ct2 * ct3) - sp[25] * (st0 * st1);

    float g0 = fmaxf(fmaf(sp[28], z, sp[32]), 0.0f);
    float g1 = fmaxf(fmaf(sp[29], z, sp[33]), 0.0f);
    float g2 = fmaxf(fmaf(sp[30], z, sp[34]), 0.0f);
    float g3 = fmaxf(fmaf(sp[31], z, sp[35]), 0.0f);

    float o0 = fmaf(sp[36], g0, fmaf(sp[37], g1, fmaf(sp[38], g2, fmaf(sp[39], g3, sp[44]))));
    float o1 = fmaf(sp[40], g0, fmaf(sp[41], g1, fmaf(sp[42], g2, fmaf(sp[43], g3, sp[45]))));
    return make_float2(o0, o1);
}

__global__ __launch_bounds__(256) void qnn_fused(
    const float4* __restrict__ x, float2* __restrict__ out,
    const float* __restrict__ W1, const float* __restrict__ b1,
    const float* __restrict__ qw, const float* __restrict__ W2,
    const float* __restrict__ b2, const float* __restrict__ W3,
    const float* __restrict__ b3, int n)
{
    __shared__ __align__(16) float sp[48];

    const float S = 2.0f * 1.4426950408889634f;  // 2*log2(e)
    int t = threadIdx.x;
    if (t < 16)      sp[t] = S * W1[t];            // rows 0..3 of W1, pre-scaled
    else if (t < 20) sp[t] = S * b1[t - 16];
    else if (t < 24) sp[t] = qw[t - 20];           // qw[0,*]
    else if (t == 24) sp[24] = cosf(qw[8]);        // cos(beta), beta = qw[2,0]
    else if (t == 25) sp[25] = sinf(qw[8]) * cosf(qw[4]) * cosf(qw[5]);
    else if (t < 28)  sp[t] = 0.0f;
    else if (t < 32) sp[t] = W2[t - 28];
    else if (t < 36) sp[t] = b2[t - 32];
    else if (t < 44) sp[t] = W3[t - 36];
    else if (t < 46) sp[t] = b3[t - 44];
    else if (t < 48) sp[t] = 0.0f;

    // Lane-transposed indices: block handles 1024 consecutive samples.
    int base = blockIdx.x * 1024 + t;

    // Issue the 4 coalesced payload loads up front (independent of sp[])
    float4 xv[4];
    #pragma unroll
    for (int k = 0; k < 4; k++) {
        int idx = base + k * 256;
        xv[k] = (idx < n) ? x[idx] : make_float4(0, 0, 0, 0);
    }

    __syncthreads();

    float2 r[4];
    #pragma unroll
    for (int k = 0; k < 4; k++)
        r[k] = sample_eval(sp, xv[k]);

    #pragma unroll
    for (int k = 0; k < 4; k++) {
        int idx = base + k * 256;
        if (idx < n) out[idx] = r[k];
    }
}

extern "C" void kernel_launch(void* const* d_in, const int* in_sizes, int n_in,
                              void* d_out, int out_size) {
    const float* x  = (const float*)d_in[0];
    const float* W1 = (const float*)d_in[1];
    const float* b1 = (const float*)d_in[2];
    const float* qw = (const float*)d_in[3];
    const float* W2 = (const float*)d_in[4];
    const float* b2 = (const float*)d_in[5];
    const float* W3 = (const float*)d_in[6];
    const float* b3 = (const float*)d_in[7];

    int n = in_sizes[0] / 4;   // batch size
    int blocks = (n + 1023) / 1024;

    qnn_fused<<<blocks, 256>>>(reinterpret_cast<const float4*>(x),
                               reinterpret_cast<float2*>(d_out),
                               W1, b1, qw, W2, b2, W3, b3, n);
}